// round 14
// baseline (speedup 1.0000x reference)
#include <cuda_runtime.h>
#include <cuda_fp16.h>
#include <cstdint>
#include <math.h>

#define N_RES 320
#define CZ 128
#define NH 4
#define HD 32
#define NN (N_RES*N_RES)   /* 102400 */
#define LOG2E 1.4426950408889634f

// ---------------- scratch (static device globals; no allocation) ----------------
__device__ __half g_qkvg[(size_t)NN*512];    // 104.9 MB : [row][kind*128 + h*32 + d], fp16
__device__ float  g_nb[(size_t)NH*NN];       // 1.6 MB   : [h][q*320+k], pre-scaled by log2(e)
__device__ __half g_wa[(size_t)NN*CZ];       // 26.2 MB  : weighted_avg, fp16
// fp16 fragment-ordered weights: [kind(5)][ks(8)][wn(4)][j(4)][lane(32)] uint2 (m16n8k16 B)
__device__ uint2 g_bh[5][8][4][4][32];       // 160 KB, L2-resident

__device__ __forceinline__ uint32_t packh2(float lo, float hi) {
  __half2 h = __floats2half2_rn(lo, hi);
  return *reinterpret_cast<uint32_t*>(&h);
}
__device__ __forceinline__ float fexp2(float x) {
  float r; asm("ex2.approx.f32 %0, %1;" : "=f"(r) : "f"(x)); return r;
}
__device__ __forceinline__ void mma_f16(float* c, const uint32_t* a, const uint32_t* b) {
  asm volatile("mma.sync.aligned.m16n8k16.row.col.f32.f16.f16.f32 "
               "{%0,%1,%2,%3}, {%4,%5,%6,%7}, {%8,%9}, {%0,%1,%2,%3};"
               : "+f"(c[0]), "+f"(c[1]), "+f"(c[2]), "+f"(c[3])
               : "r"(a[0]), "r"(a[1]), "r"(a[2]), "r"(a[3]), "r"(b[0]), "r"(b[1]));
}

#define LDH 68   /* half2-word stride for [64][64-pair] smem A tiles (bank-clean) */

// ---------------- K0: weight -> fp16 m16n8k16 B-fragment prep -------------------
__global__ void k0_prep(const float* __restrict__ qw, const float* __restrict__ kw,
                        const float* __restrict__ vw, const float* __restrict__ gw,
                        const float* __restrict__ ow) {
  int kind = blockIdx.x >> 3, ks = blockIdx.x & 7;
  const float* W = (kind == 0) ? qw : (kind == 1) ? kw : (kind == 2) ? vw : (kind == 3) ? gw : ow;
  int t = threadIdx.x;
  int wn = t >> 7, j = (t >> 5) & 3, lane = t & 31;
  int qr = lane >> 2, qc = lane & 3;
  int col = wn * 32 + j * 8 + qr;
  int k0 = ks * 16;
  uint2 v;
  v.x = packh2(W[(k0 + 2 * qc) * 128 + col], W[(k0 + 2 * qc + 1) * 128 + col]);
  v.y = packh2(W[(k0 + 2 * qc + 8) * 128 + col], W[(k0 + 2 * qc + 9) * 128 + col]);
  g_bh[kind][ks][wn][j][lane] = v;
}

// ---------------- K1: LayerNorm(affine) + nonbatched bias (warp-per-row) --------
__global__ __launch_bounds__(256) void k1_nb(const float* __restrict__ affine,
                                             const float* __restrict__ als,
                                             const float* __restrict__ alo,
                                             const float* __restrict__ f2d) {
  int w = threadIdx.x >> 5, l = threadIdx.x & 31;
  int row = blockIdx.x * 8 + w;
  const float* ar = affine + (size_t)row * CZ;

  float x[4];
  float s = 0.f, s2 = 0.f;
  #pragma unroll
  for (int m = 0; m < 4; m++) {
    x[m] = ar[l + 32 * m];
    s += x[m]; s2 += x[m] * x[m];
  }
  #pragma unroll
  for (int o = 16; o; o >>= 1) { s += __shfl_xor_sync(~0u, s, o); s2 += __shfl_xor_sync(~0u, s2, o); }
  float mean = s * (1.f / CZ);
  float var  = s2 * (1.f / CZ) - mean * mean;
  float rstd = rsqrtf(var + 1e-5f);

  float p0 = 0.f, p1 = 0.f, p2 = 0.f, p3 = 0.f;
  #pragma unroll
  for (int m = 0; m < 4; m++) {
    int c = l + 32 * m;
    float aln = (x[m] - mean) * rstd * als[c] + alo[c];
    p0 += aln * f2d[c * 4 + 0];
    p1 += aln * f2d[c * 4 + 1];
    p2 += aln * f2d[c * 4 + 2];
    p3 += aln * f2d[c * 4 + 3];
  }
  #pragma unroll
  for (int o = 16; o; o >>= 1) {
    p0 += __shfl_xor_sync(~0u, p0, o);
    p1 += __shfl_xor_sync(~0u, p1, o);
    p2 += __shfl_xor_sync(~0u, p2, o);
    p3 += __shfl_xor_sync(~0u, p3, o);
  }
  if (l == 0) {
    g_nb[(size_t)0 * NN + row] = p0 * LOG2E;
    g_nb[(size_t)1 * NN + row] = p1 * LOG2E;
    g_nb[(size_t)2 * NN + row] = p2 * LOG2E;
    g_nb[(size_t)3 * NN + row] = p3 * LOG2E;
  }
}

// ---------------- K2: fused pair-LN + all-4-kind QKVG projection (fp16 k16) -----
__global__ __launch_bounds__(256) void k2_mma(const float* __restrict__ pair,
                                              const float* __restrict__ pls,
                                              const float* __restrict__ plo) {
  extern __shared__ uint32_t sm2[];
  uint32_t* Ash2 = sm2;             // [64][LDH] half2 words

  int tid = threadIdx.x, wid = tid >> 5, lane = tid & 31;
  int wm = wid >> 2, wn = wid & 3;            // warp grid 2x4
  int qr = lane >> 2, qc = lane & 3;
  int rowBase = blockIdx.x * 64;

  float plsv[4], plov[4];
  #pragma unroll
  for (int m = 0; m < 4; m++) { plsv[m] = pls[lane + 32 * m]; plov[m] = plo[lane + 32 * m]; }
  for (int r = wid; r < 64; r += 8) {
    const float* pr = pair + (size_t)(rowBase + r) * CZ;
    float x[4];
    float s = 0.f, s2 = 0.f;
    #pragma unroll
    for (int m = 0; m < 4; m++) {
      x[m] = pr[lane + 32 * m];
      s += x[m]; s2 += x[m] * x[m];
    }
    #pragma unroll
    for (int o = 16; o; o >>= 1) { s += __shfl_xor_sync(~0u, s, o); s2 += __shfl_xor_sync(~0u, s2, o); }
    float mean = s * (1.f / CZ);
    float var  = s2 * (1.f / CZ) - mean * mean;
    float rstd = rsqrtf(var + 1e-5f);
    #pragma unroll
    for (int m = 0; m < 4; m++) {
      float y = (x[m] - mean) * rstd * plsv[m] + plov[m];
      float yp = __shfl_xor_sync(~0u, y, 1);
      if (!(lane & 1)) Ash2[r * LDH + 16 * m + (lane >> 1)] = packh2(y, yp);
    }
  }
  __syncthreads();

  for (int kind = 0; kind < 4; kind++) {
    float acc[2][4][4];
    #pragma unroll
    for (int i = 0; i < 2; i++)
      #pragma unroll
      for (int j = 0; j < 4; j++)
        #pragma unroll
        for (int e = 0; e < 4; e++) acc[i][j][e] = 0.f;

    #pragma unroll
    for (int ks = 0; ks < 8; ks++) {
      int kp0 = ks * 8;
      uint32_t af[2][4];
      #pragma unroll
      for (int i = 0; i < 2; i++) {
        int row = wm * 32 + i * 16 + qr;
        af[i][0] = Ash2[row * LDH + kp0 + qc];
        af[i][1] = Ash2[(row + 8) * LDH + kp0 + qc];
        af[i][2] = Ash2[row * LDH + kp0 + qc + 4];
        af[i][3] = Ash2[(row + 8) * LDH + kp0 + qc + 4];
      }
      #pragma unroll
      for (int j = 0; j < 4; j++) {
        uint2 b2 = g_bh[kind][ks][wn][j][lane];
        uint32_t bf[2] = { b2.x, b2.y };
        #pragma unroll
        for (int i = 0; i < 2; i++)
          mma_f16(acc[i][j], af[i], bf);
      }
    }

    int colBase = kind * 128;
    #pragma unroll
    for (int i = 0; i < 2; i++) {
      int row0 = rowBase + wm * 32 + i * 16 + qr;
      #pragma unroll
      for (int j = 0; j < 4; j++) {
        int col = colBase + wn * 32 + j * 8 + qc * 2;
        *(__half2*)(g_qkvg + (size_t)row0 * 512 + col)       = __floats2half2_rn(acc[i][j][0], acc[i][j][1]);
        *(__half2*)(g_qkvg + (size_t)(row0 + 8) * 512 + col) = __floats2half2_rn(acc[i][j][2], acc[i][j][3]);
      }
    }
  }
}

// ---------------- K3: register-flash attention, STATIC-MAX softmax --------------
// M[q] = max_k(nb+bias) precomputed per warp; chunks fully independent (no online
// rescale, no chunk max, no cross-chunk serial chain). fp16 QK+AV, exp2 domain.
#define KT2_P 328
#define VS2_P 40
#define K3_KT2  0
#define K3_VS2  (16*KT2_P)                /* 5248 */
#define K3_BIAS (K3_VS2 + 160*VS2_P)      /* +6400 = 11648 */
#define K3_FLOATS (K3_BIAS + 320)         /* 11968 words = 47872 B */

__global__ __launch_bounds__(640, 1) void k3_attn(const float* __restrict__ mask) {
  extern __shared__ uint32_t sm3[];
  uint32_t* Kh2 = sm3 + K3_KT2;        // [16 c-pairs][328]
  uint32_t* Vs2 = sm3 + K3_VS2;        // [160 key-pairs][40]
  float*    bias_s = (float*)(sm3 + K3_BIAS);

  int h = blockIdx.x, b = blockIdx.y;
  int tid = threadIdx.x, wid = tid >> 5, lane = tid & 31;
  int qr = lane >> 2, qc = lane & 3;

  #pragma unroll 2
  for (int i = 0; i < 8; i++) {
    int e = tid + i * 640;
    int cp = e & 15, key = e >> 4;
    Kh2[cp * KT2_P + key] =
      *(const uint32_t*)(g_qkvg + (size_t)(b * 320 + key) * 512 + h * 32 + 128 + 2 * cp);
  }
  #pragma unroll 2
  for (int i = 0; i < 8; i++) {
    int e = tid + i * 640;
    int kp = e >> 5, c = e & 31;
    size_t rb = (size_t)(b * 320 + 2 * kp) * 512 + h * 32 + 256 + c;
    Vs2[kp * VS2_P + c] = packh2(__half2float(g_qkvg[rb]), __half2float(g_qkvg[rb + 512]));
  }
  if (tid < 320) bias_s[tid] = LOG2E * 1e9f * (mask[b * 320 + tid] - 1.f);
  __syncthreads();

  const float scl2 = 0.17677669529663687f * LOG2E;   // qk scale, log2 domain
  int q0w = wid * 16;
  size_t rA = (size_t)(b * 320 + q0w + qr) * 512 + h * 32;
  const float* nbr0 = g_nb + (size_t)h * NN + (size_t)(q0w + qr) * 320;   // pre-scaled
  const float* nbr1 = nbr0 + 8 * 320;

  // ---- static per-row max M[q] = max_k(nb + bias), this warp's 16 rows ----
  float M0 = 0.f, M1 = 0.f;
  for (int r = 0; r < 16; r++) {
    const float* nbq = g_nb + (size_t)h * NN + (size_t)(q0w + r) * 320;
    float pm = -3.0e38f;
    #pragma unroll
    for (int t = 0; t < 10; t++) {
      int k = lane + 32 * t;
      pm = fmaxf(pm, nbq[k] + bias_s[k]);
    }
    #pragma unroll
    for (int o = 16; o; o >>= 1) pm = fmaxf(pm, __shfl_xor_sync(~0u, pm, o));
    if (r == qr) M0 = pm;
    if (r == qr + 8) M1 = pm;
  }

  uint32_t qf[2][4];
  #pragma unroll
  for (int cs = 0; cs < 2; cs++) {
    int c0 = cs * 16;
    qf[cs][0] = *(const uint32_t*)(g_qkvg + rA + c0 + 2 * qc);
    qf[cs][1] = *(const uint32_t*)(g_qkvg + rA + 8 * 512 + c0 + 2 * qc);
    qf[cs][2] = *(const uint32_t*)(g_qkvg + rA + c0 + 8 + 2 * qc);
    qf[cs][3] = *(const uint32_t*)(g_qkvg + rA + 8 * 512 + c0 + 8 + 2 * qc);
  }

  float o[4][4];
  #pragma unroll
  for (int jo = 0; jo < 4; jo++)
    #pragma unroll
    for (int e = 0; e < 4; e++) o[jo][e] = 0.f;
  float ps0 = 0.f, ps1 = 0.f;

  for (int ch = 0; ch < 5; ch++) {
    int kbase = ch * 64;

    // ---- S chunk = Q @ K^T (16 x 64), fp16 k16 ----
    float s[8][4];
    #pragma unroll
    for (int j = 0; j < 8; j++)
      #pragma unroll
      for (int e = 0; e < 4; e++) s[j][e] = 0.f;

    #pragma unroll
    for (int cs = 0; cs < 2; cs++) {
      #pragma unroll
      for (int j = 0; j < 8; j++) {
        int col = kbase + j * 8 + qr;
        uint32_t bf[2] = { Kh2[(cs * 8 + qc) * KT2_P + col],
                           Kh2[(cs * 8 + qc + 4) * KT2_P + col] };
        mma_f16(s[j], qf[cs], bf);
      }
    }

    // ---- p = exp2(s*scl2 + bias + nb - M); accumulate sums; pack fp16 ----
    uint32_t ph[8][2];
    #pragma unroll
    for (int j = 0; j < 8; j++) {
      int kk = kbase + j * 8 + qc * 2;
      float2 n0 = *(const float2*)(nbr0 + kk);
      float2 n1 = *(const float2*)(nbr1 + kk);
      float b0 = bias_s[kk], b1 = bias_s[kk + 1];
      float p0 = fexp2(s[j][0] * scl2 + (b0 + n0.x - M0));
      float p1 = fexp2(s[j][1] * scl2 + (b1 + n0.y - M0));
      float p2 = fexp2(s[j][2] * scl2 + (b0 + n1.x - M1));
      float p3 = fexp2(s[j][3] * scl2 + (b1 + n1.y - M1));
      ps0 += p0 + p1;
      ps1 += p2 + p3;
      ph[j][0] = packh2(p0, p1);
      ph[j][1] = packh2(p2, p3);
    }

    // ---- AV fp16 k16 (direct accumulate, no rescale) ----
    #pragma unroll
    for (int ks = 0; ks < 4; ks++) {
      uint32_t af[4] = { ph[2*ks][0], ph[2*ks][1], ph[2*ks+1][0], ph[2*ks+1][1] };
      int kvp = (kbase >> 1) + ks * 8;
      #pragma unroll
      for (int jo = 0; jo < 4; jo++) {
        int col = jo * 8 + qr;
        uint32_t bf[2] = { Vs2[(kvp + qc) * VS2_P + col],
                           Vs2[(kvp + qc + 4) * VS2_P + col] };
        mma_f16(o[jo], af, bf);
      }
    }
  }

  // ---- row-sum reduce (quad) + normalize + store fp16 ----
  ps0 += __shfl_xor_sync(~0u, ps0, 1); ps0 += __shfl_xor_sync(~0u, ps0, 2);
  ps1 += __shfl_xor_sync(~0u, ps1, 1); ps1 += __shfl_xor_sync(~0u, ps1, 2);
  float inv0 = 1.f / ps0, inv1 = 1.f / ps1;
  size_t row = (size_t)(b * 320 + q0w + qr);
  #pragma unroll
  for (int jo = 0; jo < 4; jo++) {
    int col = h * 32 + jo * 8 + qc * 2;
    *(__half2*)(g_wa + row * 128 + col)       = __floats2half2_rn(o[jo][0] * inv0, o[jo][1] * inv0);
    *(__half2*)(g_wa + (row + 8) * 128 + col) = __floats2half2_rn(o[jo][2] * inv1, o[jo][3] * inv1);
  }
}

// ---------------- K4: gate*sigmoid fused + output proj (fp16 k16) ---------------
__global__ __launch_bounds__(256) void k4_mma(float* __restrict__ out) {
  extern __shared__ uint32_t sm4[];
  uint32_t* Ash2 = sm4;             // [64][LDH]

  int tid = threadIdx.x, wid = tid >> 5, lane = tid & 31;
  int wm = wid >> 2, wn = wid & 3;
  int qr = lane >> 2, qc = lane & 3;
  int rowBase = blockIdx.x * 64;

  #pragma unroll
  for (int i = 0; i < 4; i++) {
    int idx = tid + i * 256;
    int r = idx >> 4, f = idx & 15;
    int row = rowBase + r;
    uint4 av = *(const uint4*)(g_wa + (size_t)row * CZ + f * 8);
    uint4 gv = *(const uint4*)(g_qkvg + (size_t)row * 512 + 384 + f * 8);
    const __half2* ah = (const __half2*)&av;
    const __half2* gh = (const __half2*)&gv;
    uint32_t hw[4];
    #pragma unroll
    for (int m = 0; m < 4; m++) {
      float2 a = __half22float2(ah[m]);
      float2 g = __half22float2(gh[m]);
      hw[m] = packh2(a.x * (1.f / (1.f + __expf(-g.x))),
                     a.y * (1.f / (1.f + __expf(-g.y))));
    }
    *(uint4*)(Ash2 + r * LDH + f * 4) = *(const uint4*)hw;
  }
  __syncthreads();

  float acc[2][4][4];
  #pragma unroll
  for (int i = 0; i < 2; i++)
    #pragma unroll
    for (int j = 0; j < 4; j++)
      #pragma unroll
      for (int e = 0; e < 4; e++) acc[i][j][e] = 0.f;

  #pragma unroll
  for (int ks = 0; ks < 8; ks++) {
    int kp0 = ks * 8;
    uint32_t af[2][4];
    #pragma unroll
    for (int i = 0; i < 2; i++) {
      int row = wm * 32 + i * 16 + qr;
      af[i][0] = Ash2[row * LDH + kp0 + qc];
      af[i][1] = Ash2[(row + 8) * LDH + kp0 + qc];
      af[i][2] = Ash2[row * LDH + kp0 + qc + 4];
      af[i][3] = Ash2[(row + 8) * LDH + kp0 + qc + 4];
    }
    #pragma unroll
    for (int j = 0; j < 4; j++) {
      uint2 b2 = g_bh[4][ks][wn][j][lane];
      uint32_t bf[2] = { b2.x, b2.y };
      #pragma unroll
      for (int i = 0; i < 2; i++)
        mma_f16(acc[i][j], af[i], bf);
    }
  }

  #pragma unroll
  for (int i = 0; i < 2; i++) {
    int row0 = rowBase + wm * 32 + i * 16 + qr;
    #pragma unroll
    for (int j = 0; j < 4; j++) {
      int col = wn * 32 + j * 8 + qc * 2;
      *(float2*)(out + (size_t)row0 * CZ + col)       = make_float2(acc[i][j][0], acc[i][j][1]);
      *(float2*)(out + (size_t)(row0 + 8) * CZ + col) = make_float2(acc[i][j][2], acc[i][j][3]);
    }
  }
}

// ---------------- launch --------------------------------------------------------
extern "C" void kernel_launch(void* const* d_in, const int* in_sizes, int n_in,
                              void* d_out, int out_size) {
  const float* pair    = (const float*)d_in[0];
  const float* affine  = (const float*)d_in[1];
  const float* mask    = (const float*)d_in[2];
  const float* pls     = (const float*)d_in[3];
  const float* plo     = (const float*)d_in[4];
  const float* als     = (const float*)d_in[5];
  const float* alo     = (const float*)d_in[6];
  const float* f2d     = (const float*)d_in[7];
  const float* qw      = (const float*)d_in[8];
  const float* kw      = (const float*)d_in[9];
  const float* vw      = (const float*)d_in[10];
  const float* gw      = (const float*)d_in[11];
  const float* ow      = (const float*)d_in[12];
  float* out = (float*)d_out;

  const int a_smem  = 64 * LDH * 4;             // 17408 B
  const int k3_smem = K3_FLOATS * 4;            // 47872 B
  cudaFuncSetAttribute(k2_mma, cudaFuncAttributeMaxDynamicSharedMemorySize, a_smem);
  cudaFuncSetAttribute(k4_mma, cudaFuncAttributeMaxDynamicSharedMemorySize, a_smem);
  cudaFuncSetAttribute(k3_attn, cudaFuncAttributeMaxDynamicSharedMemorySize, k3_smem);

  k0_prep<<<40, 512>>>(qw, kw, vw, gw, ow);
  k1_nb<<<NN / 8, 256>>>(affine, als, alo, f2d);
  k2_mma<<<NN / 64, 256, a_smem>>>(pair, pls, plo);
  k3_attn<<<dim3(NH, N_RES), 640, k3_smem>>>(mask);
  k4_mma<<<NN / 64, 256, a_smem>>>(out);
}

// round 15
// speedup vs baseline: 1.0550x; 1.0550x over previous
#include <cuda_runtime.h>
#include <cuda_fp16.h>
#include <cstdint>
#include <math.h>

#define N_RES 320
#define CZ 128
#define NH 4
#define HD 32
#define NN (N_RES*N_RES)   /* 102400 */
#define LOG2E 1.4426950408889634f

// ---------------- scratch (static device globals; no allocation) ----------------
__device__ __half g_qkvg[(size_t)NN*512];    // 104.9 MB : [row][kind*128 + h*32 + d], fp16
__device__ float  g_nb[(size_t)NH*NN];       // 1.6 MB   : [h][q*320+k], pre-scaled by log2(e)
__device__ float  g_mx[NH*N_RES];            // 5 KB     : M[h][q] = max_k nb (static softmax max)
__device__ __half g_wa[(size_t)NN*CZ];       // 26.2 MB  : weighted_avg, fp16
// fp16 fragment-ordered weights: [kind(5)][ks(8)][wn(4)][j(4)][lane(32)] uint2 (m16n8k16 B)
__device__ uint2 g_bh[5][8][4][4][32];       // 160 KB, L2-resident

__device__ __forceinline__ uint32_t packh2(float lo, float hi) {
  __half2 h = __floats2half2_rn(lo, hi);
  return *reinterpret_cast<uint32_t*>(&h);
}
__device__ __forceinline__ float fexp2(float x) {
  float r; asm("ex2.approx.f32 %0, %1;" : "=f"(r) : "f"(x)); return r;
}
__device__ __forceinline__ void mma_f16(float* c, const uint32_t* a, const uint32_t* b) {
  asm volatile("mma.sync.aligned.m16n8k16.row.col.f32.f16.f16.f32 "
               "{%0,%1,%2,%3}, {%4,%5,%6,%7}, {%8,%9}, {%0,%1,%2,%3};"
               : "+f"(c[0]), "+f"(c[1]), "+f"(c[2]), "+f"(c[3])
               : "r"(a[0]), "r"(a[1]), "r"(a[2]), "r"(a[3]), "r"(b[0]), "r"(b[1]));
}

#define LDH 68   /* half2-word stride for [64][64-pair] smem A tiles (bank-clean) */

// ---------------- K0: weight -> fp16 m16n8k16 B-fragment prep -------------------
__global__ void k0_prep(const float* __restrict__ qw, const float* __restrict__ kw,
                        const float* __restrict__ vw, const float* __restrict__ gw,
                        const float* __restrict__ ow) {
  int kind = blockIdx.x >> 3, ks = blockIdx.x & 7;
  const float* W = (kind == 0) ? qw : (kind == 1) ? kw : (kind == 2) ? vw : (kind == 3) ? gw : ow;
  int t = threadIdx.x;
  int wn = t >> 7, j = (t >> 5) & 3, lane = t & 31;
  int qr = lane >> 2, qc = lane & 3;
  int col = wn * 32 + j * 8 + qr;
  int k0 = ks * 16;
  uint2 v;
  v.x = packh2(W[(k0 + 2 * qc) * 128 + col], W[(k0 + 2 * qc + 1) * 128 + col]);
  v.y = packh2(W[(k0 + 2 * qc + 8) * 128 + col], W[(k0 + 2 * qc + 9) * 128 + col]);
  g_bh[kind][ks][wn][j][lane] = v;
}

// ---------------- K1: LayerNorm(affine) + nonbatched bias (warp-per-row) --------
__global__ __launch_bounds__(256) void k1_nb(const float* __restrict__ affine,
                                             const float* __restrict__ als,
                                             const float* __restrict__ alo,
                                             const float* __restrict__ f2d) {
  int w = threadIdx.x >> 5, l = threadIdx.x & 31;
  int row = blockIdx.x * 8 + w;
  const float* ar = affine + (size_t)row * CZ;

  float x[4];
  float s = 0.f, s2 = 0.f;
  #pragma unroll
  for (int m = 0; m < 4; m++) {
    x[m] = ar[l + 32 * m];
    s += x[m]; s2 += x[m] * x[m];
  }
  #pragma unroll
  for (int o = 16; o; o >>= 1) { s += __shfl_xor_sync(~0u, s, o); s2 += __shfl_xor_sync(~0u, s2, o); }
  float mean = s * (1.f / CZ);
  float var  = s2 * (1.f / CZ) - mean * mean;
  float rstd = rsqrtf(var + 1e-5f);

  float p0 = 0.f, p1 = 0.f, p2 = 0.f, p3 = 0.f;
  #pragma unroll
  for (int m = 0; m < 4; m++) {
    int c = l + 32 * m;
    float aln = (x[m] - mean) * rstd * als[c] + alo[c];
    p0 += aln * f2d[c * 4 + 0];
    p1 += aln * f2d[c * 4 + 1];
    p2 += aln * f2d[c * 4 + 2];
    p3 += aln * f2d[c * 4 + 3];
  }
  #pragma unroll
  for (int o = 16; o; o >>= 1) {
    p0 += __shfl_xor_sync(~0u, p0, o);
    p1 += __shfl_xor_sync(~0u, p1, o);
    p2 += __shfl_xor_sync(~0u, p2, o);
    p3 += __shfl_xor_sync(~0u, p3, o);
  }
  if (l == 0) {
    g_nb[(size_t)0 * NN + row] = p0 * LOG2E;
    g_nb[(size_t)1 * NN + row] = p1 * LOG2E;
    g_nb[(size_t)2 * NN + row] = p2 * LOG2E;
    g_nb[(size_t)3 * NN + row] = p3 * LOG2E;
  }
}

// ---------------- K1b: static softmax max M[h][q] = max_k nb[h][q][k] -----------
// 1280 (h,q) rows, one warp each. bias <= 0 so M bounds nb+bias: exp2 never
// overflows; with the ones-mask (bias==0) M is the exact R14 value.
__global__ __launch_bounds__(256) void k1b_mx() {
  int w = threadIdx.x >> 5, l = threadIdx.x & 31;
  int idx = blockIdx.x * 8 + w;            // 0..1279 = h*320 + q
  int h = idx / 320, q = idx - h * 320;
  const float* nbq = g_nb + (size_t)h * NN + (size_t)q * 320;
  float pm = -3.0e38f;
  #pragma unroll
  for (int t = 0; t < 10; t++) pm = fmaxf(pm, nbq[l + 32 * t]);
  #pragma unroll
  for (int o = 16; o; o >>= 1) pm = fmaxf(pm, __shfl_xor_sync(~0u, pm, o));
  if (l == 0) g_mx[idx] = pm;
}

// ---------------- K2: fused pair-LN + all-4-kind QKVG projection (fp16 k16) -----
// Flattened (kind,ks) loop with register double-buffered B fragments.
__global__ __launch_bounds__(256) void k2_mma(const float* __restrict__ pair,
                                              const float* __restrict__ pls,
                                              const float* __restrict__ plo) {
  extern __shared__ uint32_t sm2[];
  uint32_t* Ash2 = sm2;             // [64][LDH] half2 words

  int tid = threadIdx.x, wid = tid >> 5, lane = tid & 31;
  int wm = wid >> 2, wn = wid & 3;            // warp grid 2x4
  int qr = lane >> 2, qc = lane & 3;
  int rowBase = blockIdx.x * 64;

  float plsv[4], plov[4];
  #pragma unroll
  for (int m = 0; m < 4; m++) { plsv[m] = pls[lane + 32 * m]; plov[m] = plo[lane + 32 * m]; }
  for (int r = wid; r < 64; r += 8) {
    const float* pr = pair + (size_t)(rowBase + r) * CZ;
    float x[4];
    float s = 0.f, s2 = 0.f;
    #pragma unroll
    for (int m = 0; m < 4; m++) {
      x[m] = pr[lane + 32 * m];
      s += x[m]; s2 += x[m] * x[m];
    }
    #pragma unroll
    for (int o = 16; o; o >>= 1) { s += __shfl_xor_sync(~0u, s, o); s2 += __shfl_xor_sync(~0u, s2, o); }
    float mean = s * (1.f / CZ);
    float var  = s2 * (1.f / CZ) - mean * mean;
    float rstd = rsqrtf(var + 1e-5f);
    #pragma unroll
    for (int m = 0; m < 4; m++) {
      float y = (x[m] - mean) * rstd * plsv[m] + plov[m];
      float yp = __shfl_xor_sync(~0u, y, 1);
      if (!(lane & 1)) Ash2[r * LDH + 16 * m + (lane >> 1)] = packh2(y, yp);
    }
  }
  __syncthreads();

  float acc[2][4][4];
  #pragma unroll
  for (int i = 0; i < 2; i++)
    #pragma unroll
    for (int j = 0; j < 4; j++)
      #pragma unroll
      for (int e = 0; e < 4; e++) acc[i][j][e] = 0.f;

  uint2 bcur[4];
  #pragma unroll
  for (int j = 0; j < 4; j++) bcur[j] = g_bh[0][0][wn][j][lane];

  #pragma unroll
  for (int it = 0; it < 32; it++) {
    int kind = it >> 3, ks = it & 7;
    uint2 bnxt[4];
    if (it < 31) {
      int kn = (it + 1) >> 3, ksn = (it + 1) & 7;
      #pragma unroll
      for (int j = 0; j < 4; j++) bnxt[j] = g_bh[kn][ksn][wn][j][lane];
    }

    int kp0 = ks * 8;
    uint32_t af[2][4];
    #pragma unroll
    for (int i = 0; i < 2; i++) {
      int row = wm * 32 + i * 16 + qr;
      af[i][0] = Ash2[row * LDH + kp0 + qc];
      af[i][1] = Ash2[(row + 8) * LDH + kp0 + qc];
      af[i][2] = Ash2[row * LDH + kp0 + qc + 4];
      af[i][3] = Ash2[(row + 8) * LDH + kp0 + qc + 4];
    }
    #pragma unroll
    for (int j = 0; j < 4; j++) {
      uint32_t bf[2] = { bcur[j].x, bcur[j].y };
      #pragma unroll
      for (int i = 0; i < 2; i++)
        mma_f16(acc[i][j], af[i], bf);
    }

    if (ks == 7) {
      int colBase = kind * 128;
      #pragma unroll
      for (int i = 0; i < 2; i++) {
        int row0 = rowBase + wm * 32 + i * 16 + qr;
        #pragma unroll
        for (int j = 0; j < 4; j++) {
          int col = colBase + wn * 32 + j * 8 + qc * 2;
          *(__half2*)(g_qkvg + (size_t)row0 * 512 + col)       = __floats2half2_rn(acc[i][j][0], acc[i][j][1]);
          *(__half2*)(g_qkvg + (size_t)(row0 + 8) * 512 + col) = __floats2half2_rn(acc[i][j][2], acc[i][j][3]);
        }
      }
      #pragma unroll
      for (int i = 0; i < 2; i++)
        #pragma unroll
        for (int j = 0; j < 4; j++)
          #pragma unroll
          for (int e = 0; e < 4; e++) acc[i][j][e] = 0.f;
    }
    #pragma unroll
    for (int j = 0; j < 4; j++) bcur[j] = bnxt[j];
  }
}

// ---------------- K3: register-flash attention, precomputed static max ----------
// Chunks fully independent; M loaded from g_mx (2 scalar loads per thread).
#define KT2_P 328
#define VS2_P 40
#define K3_KT2  0
#define K3_VS2  (16*KT2_P)                /* 5248 */
#define K3_BIAS (K3_VS2 + 160*VS2_P)      /* +6400 = 11648 */
#define K3_FLOATS (K3_BIAS + 320)         /* 11968 words = 47872 B */

__global__ __launch_bounds__(640, 1) void k3_attn(const float* __restrict__ mask) {
  extern __shared__ uint32_t sm3[];
  uint32_t* Kh2 = sm3 + K3_KT2;        // [16 c-pairs][328]
  uint32_t* Vs2 = sm3 + K3_VS2;        // [160 key-pairs][40]
  float*    bias_s = (float*)(sm3 + K3_BIAS);

  int h = blockIdx.x, b = blockIdx.y;
  int tid = threadIdx.x, wid = tid >> 5, lane = tid & 31;
  int qr = lane >> 2, qc = lane & 3;

  #pragma unroll 2
  for (int i = 0; i < 8; i++) {
    int e = tid + i * 640;
    int cp = e & 15, key = e >> 4;
    Kh2[cp * KT2_P + key] =
      *(const uint32_t*)(g_qkvg + (size_t)(b * 320 + key) * 512 + h * 32 + 128 + 2 * cp);
  }
  #pragma unroll 2
  for (int i = 0; i < 8; i++) {
    int e = tid + i * 640;
    int kp = e >> 5, c = e & 31;
    size_t rb = (size_t)(b * 320 + 2 * kp) * 512 + h * 32 + 256 + c;
    Vs2[kp * VS2_P + c] = packh2(__half2float(g_qkvg[rb]), __half2float(g_qkvg[rb + 512]));
  }
  if (tid < 320) bias_s[tid] = LOG2E * 1e9f * (mask[b * 320 + tid] - 1.f);
  __syncthreads();

  const float scl2 = 0.17677669529663687f * LOG2E;   // qk scale, log2 domain
  int q0w = wid * 16;
  size_t rA = (size_t)(b * 320 + q0w + qr) * 512 + h * 32;
  const float* nbr0 = g_nb + (size_t)h * NN + (size_t)(q0w + qr) * 320;   // pre-scaled
  const float* nbr1 = nbr0 + 8 * 320;

  float M0 = g_mx[h * 320 + q0w + qr];
  float M1 = g_mx[h * 320 + q0w + qr + 8];

  uint32_t qf[2][4];
  #pragma unroll
  for (int cs = 0; cs < 2; cs++) {
    int c0 = cs * 16;
    qf[cs][0] = *(const uint32_t*)(g_qkvg + rA + c0 + 2 * qc);
    qf[cs][1] = *(const uint32_t*)(g_qkvg + rA + 8 * 512 + c0 + 2 * qc);
    qf[cs][2] = *(const uint32_t*)(g_qkvg + rA + c0 + 8 + 2 * qc);
    qf[cs][3] = *(const uint32_t*)(g_qkvg + rA + 8 * 512 + c0 + 8 + 2 * qc);
  }

  float o[4][4];
  #pragma unroll
  for (int jo = 0; jo < 4; jo++)
    #pragma unroll
    for (int e = 0; e < 4; e++) o[jo][e] = 0.f;
  float ps0 = 0.f, ps1 = 0.f;

  for (int ch = 0; ch < 5; ch++) {
    int kbase = ch * 64;

    float s[8][4];
    #pragma unroll
    for (int j = 0; j < 8; j++)
      #pragma unroll
      for (int e = 0; e < 4; e++) s[j][e] = 0.f;

    #pragma unroll
    for (int cs = 0; cs < 2; cs++) {
      #pragma unroll
      for (int j = 0; j < 8; j++) {
        int col = kbase + j * 8 + qr;
        uint32_t bf[2] = { Kh2[(cs * 8 + qc) * KT2_P + col],
                           Kh2[(cs * 8 + qc + 4) * KT2_P + col] };
        mma_f16(s[j], qf[cs], bf);
      }
    }

    uint32_t ph[8][2];
    #pragma unroll
    for (int j = 0; j < 8; j++) {
      int kk = kbase + j * 8 + qc * 2;
      float2 n0 = *(const float2*)(nbr0 + kk);
      float2 n1 = *(const float2*)(nbr1 + kk);
      float b0 = bias_s[kk], b1 = bias_s[kk + 1];
      float p0 = fexp2(s[j][0] * scl2 + (b0 + n0.x - M0));
      float p1 = fexp2(s[j][1] * scl2 + (b1 + n0.y - M0));
      float p2 = fexp2(s[j][2] * scl2 + (b0 + n1.x - M1));
      float p3 = fexp2(s[j][3] * scl2 + (b1 + n1.y - M1));
      ps0 += p0 + p1;
      ps1 += p2 + p3;
      ph[j][0] = packh2(p0, p1);
      ph[j][1] = packh2(p2, p3);
    }

    #pragma unroll
    for (int ks = 0; ks < 4; ks++) {
      uint32_t af[4] = { ph[2*ks][0], ph[2*ks][1], ph[2*ks+1][0], ph[2*ks+1][1] };
      int kvp = (kbase >> 1) + ks * 8;
      #pragma unroll
      for (int jo = 0; jo < 4; jo++) {
        int col = jo * 8 + qr;
        uint32_t bf[2] = { Vs2[(kvp + qc) * VS2_P + col],
                           Vs2[(kvp + qc + 4) * VS2_P + col] };
        mma_f16(o[jo], af, bf);
      }
    }
  }

  ps0 += __shfl_xor_sync(~0u, ps0, 1); ps0 += __shfl_xor_sync(~0u, ps0, 2);
  ps1 += __shfl_xor_sync(~0u, ps1, 1); ps1 += __shfl_xor_sync(~0u, ps1, 2);
  float inv0 = 1.f / ps0, inv1 = 1.f / ps1;
  size_t row = (size_t)(b * 320 + q0w + qr);
  #pragma unroll
  for (int jo = 0; jo < 4; jo++) {
    int col = h * 32 + jo * 8 + qc * 2;
    *(__half2*)(g_wa + row * 128 + col)       = __floats2half2_rn(o[jo][0] * inv0, o[jo][1] * inv0);
    *(__half2*)(g_wa + (row + 8) * 128 + col) = __floats2half2_rn(o[jo][2] * inv1, o[jo][3] * inv1);
  }
}

// ---------------- K4: gate*sigmoid fused + output proj (fp16 k16) ---------------
__global__ __launch_bounds__(256) void k4_mma(float* __restrict__ out) {
  extern __shared__ uint32_t sm4[];
  uint32_t* Ash2 = sm4;             // [64][LDH]

  int tid = threadIdx.x, wid = tid >> 5, lane = tid & 31;
  int wm = wid >> 2, wn = wid & 3;
  int qr = lane >> 2, qc = lane & 3;
  int rowBase = blockIdx.x * 64;

  #pragma unroll
  for (int i = 0; i < 4; i++) {
    int idx = tid + i * 256;
    int r = idx >> 4, f = idx & 15;
    int row = rowBase + r;
    uint4 av = *(const uint4*)(g_wa + (size_t)row * CZ + f * 8);
    uint4 gv = *(const uint4*)(g_qkvg + (size_t)row * 512 + 384 + f * 8);
    const __half2* ah = (const __half2*)&av;
    const __half2* gh = (const __half2*)&gv;
    uint32_t hw[4];
    #pragma unroll
    for (int m = 0; m < 4; m++) {
      float2 a = __half22float2(ah[m]);
      float2 g = __half22float2(gh[m]);
      hw[m] = packh2(a.x * (1.f / (1.f + __expf(-g.x))),
                     a.y * (1.f / (1.f + __expf(-g.y))));
    }
    *(uint4*)(Ash2 + r * LDH + f * 4) = *(const uint4*)hw;
  }
  __syncthreads();

  float acc[2][4][4];
  #pragma unroll
  for (int i = 0; i < 2; i++)
    #pragma unroll
    for (int j = 0; j < 4; j++)
      #pragma unroll
      for (int e = 0; e < 4; e++) acc[i][j][e] = 0.f;

  #pragma unroll
  for (int ks = 0; ks < 8; ks++) {
    int kp0 = ks * 8;
    uint32_t af[2][4];
    #pragma unroll
    for (int i = 0; i < 2; i++) {
      int row = wm * 32 + i * 16 + qr;
      af[i][0] = Ash2[row * LDH + kp0 + qc];
      af[i][1] = Ash2[(row + 8) * LDH + kp0 + qc];
      af[i][2] = Ash2[row * LDH + kp0 + qc + 4];
      af[i][3] = Ash2[(row + 8) * LDH + kp0 + qc + 4];
    }
    #pragma unroll
    for (int j = 0; j < 4; j++) {
      uint2 b2 = g_bh[4][ks][wn][j][lane];
      uint32_t bf[2] = { b2.x, b2.y };
      #pragma unroll
      for (int i = 0; i < 2; i++)
        mma_f16(acc[i][j], af[i], bf);
    }
  }

  #pragma unroll
  for (int i = 0; i < 2; i++) {
    int row0 = rowBase + wm * 32 + i * 16 + qr;
    #pragma unroll
    for (int j = 0; j < 4; j++) {
      int col = wn * 32 + j * 8 + qc * 2;
      *(float2*)(out + (size_t)row0 * CZ + col)       = make_float2(acc[i][j][0], acc[i][j][1]);
      *(float2*)(out + (size_t)(row0 + 8) * CZ + col) = make_float2(acc[i][j][2], acc[i][j][3]);
    }
  }
}

// ---------------- launch --------------------------------------------------------
extern "C" void kernel_launch(void* const* d_in, const int* in_sizes, int n_in,
                              void* d_out, int out_size) {
  const float* pair    = (const float*)d_in[0];
  const float* affine  = (const float*)d_in[1];
  const float* mask    = (const float*)d_in[2];
  const float* pls     = (const float*)d_in[3];
  const float* plo     = (const float*)d_in[4];
  const float* als     = (const float*)d_in[5];
  const float* alo     = (const float*)d_in[6];
  const float* f2d     = (const float*)d_in[7];
  const float* qw      = (const float*)d_in[8];
  const float* kw      = (const float*)d_in[9];
  const float* vw      = (const float*)d_in[10];
  const float* gw      = (const float*)d_in[11];
  const float* ow      = (const float*)d_in[12];
  float* out = (float*)d_out;

  const int a_smem  = 64 * LDH * 4;             // 17408 B
  const int k3_smem = K3_FLOATS * 4;            // 47872 B
  cudaFuncSetAttribute(k2_mma, cudaFuncAttributeMaxDynamicSharedMemorySize, a_smem);
  cudaFuncSetAttribute(k4_mma, cudaFuncAttributeMaxDynamicSharedMemorySize, a_smem);
  cudaFuncSetAttribute(k3_attn, cudaFuncAttributeMaxDynamicSharedMemorySize, k3_smem);

  k0_prep<<<40, 512>>>(qw, kw, vw, gw, ow);
  k1_nb<<<NN / 8, 256>>>(affine, als, alo, f2d);
  k1b_mx<<<160, 256>>>();
  k2_mma<<<NN / 64, 256, a_smem>>>(pair, pls, plo);
  k3_attn<<<dim3(NH, N_RES), 640, k3_smem>>>(mask);
  k4_mma<<<NN / 64, 256, a_smem>>>(out);
}